// round 2
// baseline (speedup 1.0000x reference)
#include <cuda_runtime.h>

#define NMAX 100000
#define EMAX 1600000
#define FD 32

// scratch (static device globals — no allocation allowed)
__device__ float g_src_feat[NMAX * FD];
__device__ float g_dst_feat[NMAX * FD];
__device__ float g_agg[NMAX * FD];
__device__ float g_deg[NMAX];
__device__ float g_src2[NMAX * FD];
__device__ float g_dst2[NMAX * FD];

// K1: per node: src_feat = f @ Ws^T ; dst_feat = f @ Wd^T + bd ; zero agg/deg
__global__ void k_node1(const float* __restrict__ feat, const float* __restrict__ Ws,
                        const float* __restrict__ Wd, const float* __restrict__ bd, int N)
{
    __shared__ float sWs[32][33];
    __shared__ float sWd[32][33];
    __shared__ float sF[8][32];
    int t = threadIdx.x;
    for (int i = t; i < 1024; i += blockDim.x) {
        sWs[i >> 5][i & 31] = Ws[i];
        sWd[i >> 5][i & 31] = Wd[i];
    }
    __syncthreads();
    int lane = t & 31, w = t >> 5;
    float bdi = bd[lane];
    int node = blockIdx.x * 8 + w;
    int stride = gridDim.x * 8;
    for (; node < N; node += stride) {
        sF[w][lane] = feat[node * 32 + lane];
        __syncwarp();
        float accS = 0.f, accD = bdi;
        #pragma unroll
        for (int j = 0; j < 32; j++) {
            float fj = sF[w][j];
            accS += sWs[lane][j] * fj;
            accD += sWd[lane][j] * fj;
        }
        g_src_feat[node * 32 + lane] = accS;
        g_dst_feat[node * 32 + lane] = accD;
        g_agg[node * 32 + lane] = 0.f;
        if (lane == 0) g_deg[node] = 0.f;
        __syncwarp();
    }
}

// K2: warp per edge: agg[dst] += src_feat[src] (coalesced 128B row per warp);
//     lane 0 counts degree.
__global__ void k_scatter(const int* __restrict__ src, const int* __restrict__ dst, int E)
{
    int gt = blockIdx.x * blockDim.x + threadIdx.x;
    int e = gt >> 5;
    if (e >= E) return;
    int lane = gt & 31;
    int s = __ldg(&src[e]);
    int d = __ldg(&dst[e]);
    float v = g_src_feat[s * 32 + lane];
    atomicAdd(&g_agg[d * 32 + lane], v);
    if (lane == 0) atomicAdd(&g_deg[d], 1.0f);
}

// K3: per node: a = agg + deg*dst_feat ; out = a @ Wr^T + br ;
//     src2 = out @ Ws^T ; dst2 = out @ Wd^T + bd
__global__ void k_node2(const float* __restrict__ Wr, const float* __restrict__ br,
                        const float* __restrict__ Ws, const float* __restrict__ Wd,
                        const float* __restrict__ bd, int N)
{
    __shared__ float sWr[32][33];
    __shared__ float sWs[32][33];
    __shared__ float sWd[32][33];
    __shared__ float sA[8][32];
    __shared__ float sO[8][32];
    int t = threadIdx.x;
    for (int i = t; i < 1024; i += blockDim.x) {
        sWr[i >> 5][i & 31] = Wr[i];
        sWs[i >> 5][i & 31] = Ws[i];
        sWd[i >> 5][i & 31] = Wd[i];
    }
    __syncthreads();
    int lane = t & 31, w = t >> 5;
    float bri = br[lane], bdi = bd[lane];
    int node = blockIdx.x * 8 + w;
    int stride = gridDim.x * 8;
    for (; node < N; node += stride) {
        float deg = g_deg[node];
        float a = g_agg[node * 32 + lane] + deg * g_dst_feat[node * 32 + lane];
        sA[w][lane] = a;
        __syncwarp();
        float o = bri;
        #pragma unroll
        for (int j = 0; j < 32; j++) o += sWr[lane][j] * sA[w][j];
        sO[w][lane] = o;
        __syncwarp();
        float s2 = 0.f, d2 = bdi;
        #pragma unroll
        for (int j = 0; j < 32; j++) {
            float fo = sO[w][j];
            s2 += sWs[lane][j] * fo;
            d2 += sWd[lane][j] * fo;
        }
        g_src2[node * 32 + lane] = s2;
        g_dst2[node * 32 + lane] = d2;
        __syncwarp();
    }
}

// K4: 8 threads per edge, float4 per thread: out[e] = src2[src[e]] + dst2[dst[e]]
__global__ void k_out(const int* __restrict__ src, const int* __restrict__ dst,
                      float4* __restrict__ out, int E)
{
    int gt = blockIdx.x * blockDim.x + threadIdx.x;
    if (gt >= E * 8) return;
    int e = gt >> 3;
    int q = gt & 7;
    int s = __ldg(&src[e]);
    int d = __ldg(&dst[e]);
    const float4* ps = reinterpret_cast<const float4*>(&g_src2[s * 32 + q * 4]);
    const float4* pd = reinterpret_cast<const float4*>(&g_dst2[d * 32 + q * 4]);
    float4 a = *ps;
    float4 b = *pd;
    out[gt] = make_float4(a.x + b.x, a.y + b.y, a.z + b.z, a.w + b.w);
}

extern "C" void kernel_launch(void* const* d_in, const int* in_sizes, int n_in,
                              void* d_out, int out_size)
{
    const float* feat = (const float*)d_in[0];
    const int*   src  = (const int*)d_in[1];
    const int*   dst  = (const int*)d_in[2];
    const float* Ws   = (const float*)d_in[3];
    const float* Wd   = (const float*)d_in[4];
    const float* bd   = (const float*)d_in[5];
    const float* Wr   = (const float*)d_in[6];
    const float* br   = (const float*)d_in[7];

    int N = in_sizes[0] / FD;
    int E = in_sizes[1];

    int nodeBlocks = (N + 7) / 8;                 // 8 warps per 256-thread block
    k_node1<<<nodeBlocks, 256>>>(feat, Ws, Wd, bd, N);

    int scatterBlocks = (E * 32 + 255) / 256;     // warp per edge
    k_scatter<<<scatterBlocks, 256>>>(src, dst, E);

    k_node2<<<nodeBlocks, 256>>>(Wr, br, Ws, Wd, bd, N);

    int outBlocks = (E * 8 + 255) / 256;          // 8 threads (float4 each) per edge
    k_out<<<outBlocks, 256>>>(src, dst, (float4*)d_out, E);
}

// round 3
// speedup vs baseline: 1.4128x; 1.4128x over previous
#include <cuda_runtime.h>

#define NMAX 100000
#define EMAX 1600000
#define FD 32
#define SCAN_CHUNK 512

// scratch (static device globals — no allocation allowed)
__device__ float g_src_feat[NMAX * FD];
__device__ float g_dst_feat[NMAX * FD];
__device__ float g_src2[NMAX * FD];
__device__ float g_dst2[NMAX * FD];
__device__ int   g_cnt[NMAX];      // in-degree histogram
__device__ int   g_off[NMAX];      // CSR offsets (exclusive scan of cnt)
__device__ int   g_cur[NMAX];      // running cursor for bucket build
__device__ int   g_partial[256];   // scan block partials
__device__ int   g_csr[EMAX];      // src node ids grouped by dst

// K1: per node: src_feat = f @ Ws^T ; dst_feat = f @ Wd^T + bd ; zero cnt
__global__ void k_node1(const float* __restrict__ feat, const float* __restrict__ Ws,
                        const float* __restrict__ Wd, const float* __restrict__ bd, int N)
{
    __shared__ float sWs[32][33];
    __shared__ float sWd[32][33];
    __shared__ float sF[8][32];
    int t = threadIdx.x;
    for (int i = t; i < 1024; i += blockDim.x) {
        sWs[i >> 5][i & 31] = Ws[i];
        sWd[i >> 5][i & 31] = Wd[i];
    }
    __syncthreads();
    int lane = t & 31, w = t >> 5;
    float bdi = bd[lane];
    int node = blockIdx.x * 8 + w;
    int stride = gridDim.x * 8;
    for (; node < N; node += stride) {
        sF[w][lane] = feat[node * 32 + lane];
        __syncwarp();
        float accS = 0.f, accD = bdi;
        #pragma unroll
        for (int j = 0; j < 32; j++) {
            float fj = sF[w][j];
            accS += sWs[lane][j] * fj;
            accD += sWd[lane][j] * fj;
        }
        g_src_feat[node * 32 + lane] = accS;
        g_dst_feat[node * 32 + lane] = accD;
        if (lane == 0) g_cnt[node] = 0;
        __syncwarp();
    }
}

// Histogram of dst (in-degree)
__global__ void k_hist(const int* __restrict__ dst, int E)
{
    int e = blockIdx.x * blockDim.x + threadIdx.x;
    if (e < E) atomicAdd(&g_cnt[dst[e]], 1);
}

// Scan phase A: per-block sums of g_cnt chunks
__global__ void k_scan_a(int N)
{
    __shared__ int sh[SCAN_CHUNK];
    int i = blockIdx.x * SCAN_CHUNK + threadIdx.x;
    sh[threadIdx.x] = (i < N) ? g_cnt[i] : 0;
    __syncthreads();
    for (int d = SCAN_CHUNK / 2; d > 0; d >>= 1) {
        if (threadIdx.x < d) sh[threadIdx.x] += sh[threadIdx.x + d];
        __syncthreads();
    }
    if (threadIdx.x == 0) g_partial[blockIdx.x] = sh[0];
}

// Scan phase B: exclusive scan of block partials (single block, P <= 256)
__global__ void k_scan_b(int P)
{
    __shared__ int sh[256];
    int t = threadIdx.x;
    int own = (t < P) ? g_partial[t] : 0;
    sh[t] = own;
    __syncthreads();
    for (int d = 1; d < 256; d <<= 1) {
        int v = (t >= d) ? sh[t - d] : 0;
        __syncthreads();
        sh[t] += v;
        __syncthreads();
    }
    if (t < P) g_partial[t] = sh[t] - own;   // exclusive
}

// Scan phase C: per-block exclusive scan + base -> g_off, g_cur
__global__ void k_scan_c(int N)
{
    __shared__ int sh[SCAN_CHUNK];
    int t = threadIdx.x;
    int i = blockIdx.x * SCAN_CHUNK + t;
    int own = (i < N) ? g_cnt[i] : 0;
    sh[t] = own;
    __syncthreads();
    for (int d = 1; d < SCAN_CHUNK; d <<= 1) {
        int v = (t >= d) ? sh[t - d] : 0;
        __syncthreads();
        sh[t] += v;
        __syncthreads();
    }
    if (i < N) {
        int off = sh[t] - own + g_partial[blockIdx.x];
        g_off[i] = off;
        g_cur[i] = off;
    }
}

// Bucket build: group src ids by dst
__global__ void k_build(const int* __restrict__ src, const int* __restrict__ dst, int E)
{
    int e = blockIdx.x * blockDim.x + threadIdx.x;
    if (e >= E) return;
    int d = dst[e];
    int pos = atomicAdd(&g_cur[d], 1);
    g_csr[pos] = src[e];
}

// Fused aggregate + node2: warp per node.
// a = sum_{u in csr[v]} src_feat[u] + deg*dst_feat[v]
// out = a @ Wr^T + br ; src2 = out @ Ws^T ; dst2 = out @ Wd^T + bd
__global__ void k_agg_node2(const float* __restrict__ Wr, const float* __restrict__ br,
                            const float* __restrict__ Ws, const float* __restrict__ Wd,
                            const float* __restrict__ bd, int N)
{
    __shared__ float sWr[32][33];
    __shared__ float sWs[32][33];
    __shared__ float sWd[32][33];
    __shared__ float sA[8][32];
    __shared__ float sO[8][32];
    int t = threadIdx.x;
    for (int i = t; i < 1024; i += blockDim.x) {
        sWr[i >> 5][i & 31] = Wr[i];
        sWs[i >> 5][i & 31] = Ws[i];
        sWd[i >> 5][i & 31] = Wd[i];
    }
    __syncthreads();
    int lane = t & 31, w = t >> 5;
    float bri = br[lane], bdi = bd[lane];
    int node = blockIdx.x * 8 + w;
    int stride = gridDim.x * 8;
    for (; node < N; node += stride) {
        int off = g_off[node];
        int cnt = g_cnt[node];
        float acc = 0.f;
        for (int base = 0; base < cnt; base += 32) {
            int idx = base + lane;
            int id = (idx < cnt) ? g_csr[off + idx] : 0;
            int m = min(32, cnt - base);
            #pragma unroll 4
            for (int j = 0; j < m; j++) {
                int s = __shfl_sync(0xffffffffu, id, j);
                acc += g_src_feat[s * 32 + lane];
            }
        }
        float a = acc + (float)cnt * g_dst_feat[node * 32 + lane];
        sA[w][lane] = a;
        __syncwarp();
        float o = bri;
        #pragma unroll
        for (int j = 0; j < 32; j++) o += sWr[lane][j] * sA[w][j];
        sO[w][lane] = o;
        __syncwarp();
        float s2 = 0.f, d2 = bdi;
        #pragma unroll
        for (int j = 0; j < 32; j++) {
            float fo = sO[w][j];
            s2 += sWs[lane][j] * fo;
            d2 += sWd[lane][j] * fo;
        }
        g_src2[node * 32 + lane] = s2;
        g_dst2[node * 32 + lane] = d2;
        __syncwarp();
    }
}

// K4: 8 threads per edge, float4 per thread: out[e] = src2[src[e]] + dst2[dst[e]]
__global__ void k_out(const int* __restrict__ src, const int* __restrict__ dst,
                      float4* __restrict__ out, int E)
{
    int gt = blockIdx.x * blockDim.x + threadIdx.x;
    if (gt >= E * 8) return;
    int e = gt >> 3;
    int q = gt & 7;
    int s = __ldg(&src[e]);
    int d = __ldg(&dst[e]);
    const float4* ps = reinterpret_cast<const float4*>(&g_src2[s * 32 + q * 4]);
    const float4* pd = reinterpret_cast<const float4*>(&g_dst2[d * 32 + q * 4]);
    float4 a = *ps;
    float4 b = *pd;
    out[gt] = make_float4(a.x + b.x, a.y + b.y, a.z + b.z, a.w + b.w);
}

extern "C" void kernel_launch(void* const* d_in, const int* in_sizes, int n_in,
                              void* d_out, int out_size)
{
    const float* feat = (const float*)d_in[0];
    const int*   src  = (const int*)d_in[1];
    const int*   dst  = (const int*)d_in[2];
    const float* Ws   = (const float*)d_in[3];
    const float* Wd   = (const float*)d_in[4];
    const float* bd   = (const float*)d_in[5];
    const float* Wr   = (const float*)d_in[6];
    const float* br   = (const float*)d_in[7];

    int N = in_sizes[0] / FD;
    int E = in_sizes[1];

    int nodeBlocks = (N + 7) / 8;
    k_node1<<<nodeBlocks, 256>>>(feat, Ws, Wd, bd, N);

    int eBlocks = (E + 255) / 256;
    k_hist<<<eBlocks, 256>>>(dst, E);

    int P = (N + SCAN_CHUNK - 1) / SCAN_CHUNK;   // 196 for N=100K (<=256)
    k_scan_a<<<P, SCAN_CHUNK>>>(N);
    k_scan_b<<<1, 256>>>(P);
    k_scan_c<<<P, SCAN_CHUNK>>>(N);

    k_build<<<eBlocks, 256>>>(src, dst, E);

    k_agg_node2<<<nodeBlocks, 256>>>(Wr, br, Ws, Wd, bd, N);

    int outBlocks = (E * 8 + 255) / 256;
    k_out<<<outBlocks, 256>>>(src, dst, (float4*)d_out, E);
}